// round 4
// baseline (speedup 1.0000x reference)
#include <cuda_runtime.h>
#include <math.h>

#define BB 16
#define AA 3
#define HH 80
#define WW 80
#define NC 80
#define CH 85
#define MGT 32
#define NCELL (BB*AA*HH*WW)          // 307200
#define CELLS_PER_B (AA*HH*WW)       // 19200
#define NCHUNK (NCELL/256)           // 1200
#define CHUNKS_PER_B (CELLS_PER_B/256) // 75
#define EPSF 1e-8f
#define INPUT_SIZE 640.0f
#define IGN_IOU 0.5f

// ---- device scratch (zero-initialized at module load; re-zeroed by finalize
//      each launch so graph replays are deterministic) ----
__device__ float4   g_gt[BB * MGT];     // per-batch GT boxes (xyxy)
__device__ int      g_cnt[BB];
__device__ double   g_acc[6];           // npos, giou_sum, pos_obj, neg_obj, nneg, cls_sum
__device__ unsigned g_bar_arrive;
__device__ unsigned g_bar_gen;
__device__ unsigned g_done;

__device__ __forceinline__ float softplusf(float x) {
    return fmaxf(x, 0.0f) + log1pf(expf(-fabsf(x)));
}

__device__ __forceinline__ float warp_sum(float v) {
    #pragma unroll
    for (int o = 16; o > 0; o >>= 1) v += __shfl_xor_sync(0xffffffffu, v, o);
    return v;
}

__global__ void __launch_bounds__(256)
k_all(const float* __restrict__ preds, const float* __restrict__ targets,
      float* __restrict__ out, int G) {
    const float AWv[3] = {10.0f, 16.0f, 33.0f};
    const float AHv[3] = {13.0f, 30.0f, 23.0f};
    const int tid = threadIdx.x;
    const int bid = blockIdx.x;

    // ================= Phase 1: gather GT boxes =================
    for (int idx = bid * 256 + tid; idx < NCELL; idx += G * 256) {
        float tobj = __ldg(&targets[(size_t)idx * CH + 4]);
        if (tobj > 0.0f) {
            int b  = idx / CELLS_PER_B;
            int r  = idx % CELLS_PER_B;
            int a  = r / (HH * WW);
            int hw = r % (HH * WW);
            float wx = (float)(hw % WW), hy = (float)(hw / WW);
            const float* t = targets + (size_t)idx * CH;
            float cx = (t[0] + wx) * (1.0f / (float)WW);
            float cy = (t[1] + hy) * (1.0f / (float)HH);
            float bw = AWv[a] * expf(t[2]) * (1.0f / INPUT_SIZE);
            float bh = AHv[a] * expf(t[3]) * (1.0f / INPUT_SIZE);
            int slot = atomicAdd(&g_cnt[b], 1);
            if (slot < MGT)
                g_gt[b * MGT + slot] = make_float4(cx - 0.5f * bw, cy - 0.5f * bh,
                                                   cx + 0.5f * bw, cy + 0.5f * bh);
        }
    }

    // ================= Grid barrier (all G blocks co-resident) =================
    __syncthreads();
    if (tid == 0) {
        __threadfence();
        unsigned old = *(volatile unsigned*)&g_bar_gen;
        if (atomicAdd(&g_bar_arrive, 1) == (unsigned)(G - 1)) {
            g_bar_arrive = 0;
            __threadfence();
            atomicAdd(&g_bar_gen, 1);
        } else {
            while (*(volatile unsigned*)&g_bar_gen == old) __nanosleep(64);
        }
        __threadfence();
    }
    __syncthreads();

    // ================= Phase 2: per-cell losses =================
    __shared__ float4 s_gt[MGT];
    __shared__ int    s_cnt;
    __shared__ float  s_red[6][8];

    float acc[6] = {0.f, 0.f, 0.f, 0.f, 0.f, 0.f};

    for (int c = bid; c < NCHUNK; c += G) {
        __syncthreads();                      // protect s_gt from prior iteration
        int b = c / CHUNKS_PER_B;
        if (tid < MGT) s_gt[tid] = g_gt[b * MGT + tid];
        if (tid == 0)  s_cnt = min(g_cnt[b], MGT);
        __syncthreads();

        int idx = c * 256 + tid;
        int r   = idx % CELLS_PER_B;
        int a   = r / (HH * WW);
        int hw  = r % (HH * WW);
        float wx = (float)(hw % WW), hy = (float)(hw / WW);
        float aw = AWv[a], ah = AHv[a];

        const float* p = preds   + (size_t)idx * CH;
        const float* t = targets + (size_t)idx * CH;

        float ptx = p[0], pty = p[1], ptw = p[2], pth = p[3], pobj = p[4];
        float ttx = t[0], tty = t[1], ttw = t[2], tth = t[3], tobj = t[4];

        // pred box
        float sx = 1.0f / (1.0f + expf(-ptx));
        float sy = 1.0f / (1.0f + expf(-pty));
        float pcx = (sx + wx) * (1.0f / (float)WW);
        float pcy = (sy + hy) * (1.0f / (float)HH);
        float pbw = aw * expf(ptw) * (1.0f / INPUT_SIZE);
        float pbh = ah * expf(pth) * (1.0f / INPUT_SIZE);
        float px1 = pcx - 0.5f * pbw, py1 = pcy - 0.5f * pbh;
        float px2 = pcx + 0.5f * pbw, py2 = pcy + 0.5f * pbh;

        // target box
        float tcx = (ttx + wx) * (1.0f / (float)WW);
        float tcy = (tty + hy) * (1.0f / (float)HH);
        float tbw = aw * expf(ttw) * (1.0f / INPUT_SIZE);
        float tbh = ah * expf(tth) * (1.0f / INPUT_SIZE);
        float tx1 = tcx - 0.5f * tbw, ty1 = tcy - 0.5f * tbh;
        float tx2 = tcx + 0.5f * tbw, ty2 = tcy + 0.5f * tbh;

        float areaP = (px2 - px1) * (py2 - py1);

        // max IoU vs this batch's GT boxes
        float best = -1.0f;
        int cnt = s_cnt;
        #pragma unroll 8
        for (int i = 0; i < cnt; i++) {
            float4 g = s_gt[i];
            float areaG = (g.z - g.x) * (g.w - g.y);
            float iw = fmaxf(fminf(px2, g.z) - fmaxf(px1, g.x), 0.0f);
            float ih = fmaxf(fminf(py2, g.w) - fmaxf(py1, g.y), 0.0f);
            float inter = iw * ih;
            float iou = inter / (areaP + areaG - inter + EPSF);
            best = fmaxf(best, iou);
        }

        bool pos = tobj > 0.0f;
        bool ign = best > IGN_IOU;
        float posf = pos ? 1.0f : 0.0f;
        float negf = (!pos && !ign) ? 1.0f : 0.0f;

        // GIoU loss
        float areaT = (tx2 - tx1) * (ty2 - ty1);
        float iw = fmaxf(fminf(px2, tx2) - fmaxf(px1, tx1), 0.0f);
        float ih = fmaxf(fminf(py2, ty2) - fmaxf(py1, ty1), 0.0f);
        float inter = iw * ih;
        float uni  = areaP + areaT - inter;
        float iou  = inter / (uni + EPSF);
        float cw  = fmaxf(fmaxf(px2, tx2) - fminf(px1, tx1), 0.0f);
        float chh = fmaxf(fmaxf(py2, ty2) - fminf(py1, ty1), 0.0f);
        float areaC = cw * chh;
        float giou_l = 1.0f - (iou - (areaC - uni) / (areaC + EPSF));

        // obj BCE
        float obj_l = softplusf(pobj) - pobj * tobj;

        // cls BCE — only read 80 channels for positive cells (512 / 307200)
        float cls_sum = 0.0f;
        if (pos) {
            #pragma unroll 4
            for (int cc = 0; cc < NC; cc++) {
                float x  = __ldg(&p[5 + cc]);
                float tc = __ldg(&t[5 + cc]);
                cls_sum += softplusf(x) - x * tc;
            }
        }

        acc[0] += posf;
        acc[1] += giou_l * posf;
        acc[2] += obj_l * posf;
        acc[3] += obj_l * negf;
        acc[4] += negf;
        acc[5] += cls_sum;
    }

    // ================= Block reduction =================
    int lane = tid & 31, wid = tid >> 5;
    #pragma unroll
    for (int k = 0; k < 6; k++) {
        float v = warp_sum(acc[k]);
        if (lane == 0) s_red[k][wid] = v;
    }
    __syncthreads();
    if (wid == 0) {
        #pragma unroll
        for (int k = 0; k < 6; k++) {
            float v = (lane < 8) ? s_red[k][lane] : 0.0f;
            v = warp_sum(v);
            if (lane == 0) atomicAdd(&g_acc[k], (double)v);
        }
    }
    __syncthreads();

    // ================= Last-block finalize + self-clean =================
    if (tid == 0) {
        __threadfence();
        if (atomicAdd(&g_done, 1) == (unsigned)(G - 1)) {
            double npos = atomicAdd(&g_acc[0], 0.0);
            double gsum = atomicAdd(&g_acc[1], 0.0);
            double pobjs = atomicAdd(&g_acc[2], 0.0);
            double nobjs = atomicAdd(&g_acc[3], 0.0);
            double nneg = atomicAdd(&g_acc[4], 0.0);
            double csum = atomicAdd(&g_acc[5], 0.0);
            float giou_v = (float)(gsum / (npos + (double)EPSF));
            float obj_v  = (float)((5.0 * pobjs + nobjs) / (5.0 * npos + nneg + (double)EPSF));
            float cls_v  = (float)(csum / (npos + (double)EPSF));
            out[0] = giou_v + obj_v + cls_v;
            out[1] = giou_v;
            out[2] = obj_v;
            out[3] = cls_v;
            // re-zero scratch for next graph replay
            #pragma unroll
            for (int k = 0; k < 6; k++) g_acc[k] = 0.0;
            #pragma unroll
            for (int b = 0; b < BB; b++) g_cnt[b] = 0;
            g_done = 0;
            __threadfence();
        }
    }
}

extern "C" void kernel_launch(void* const* d_in, const int* in_sizes, int n_in,
                              void* d_out, int out_size) {
    const float* preds   = (const float*)d_in[0];
    const float* targets = (const float*)d_in[1];
    float* out = (float*)d_out;

    int dev = 0;
    cudaGetDevice(&dev);
    int sms = 148;
    cudaDeviceGetAttribute(&sms, cudaDevAttrMultiProcessorCount, dev);
    int occ = 1;
    cudaOccupancyMaxActiveBlocksPerMultiprocessor(&occ, k_all, 256, 0);
    if (occ < 1) occ = 1;
    long long g = (long long)sms * occ;
    if (g > NCHUNK) g = NCHUNK;
    int G = (int)g;

    k_all<<<G, 256>>>(preds, targets, out, G);
}

// round 5
// speedup vs baseline: 1.8918x; 1.8918x over previous
#include <cuda_runtime.h>
#include <math.h>

#define BB 16
#define AA 3
#define HH 80
#define WW 80
#define NC 80
#define CH 85
#define MGT 32
#define NCELL (BB*AA*HH*WW)            // 307200
#define CELLS_PER_B (AA*HH*WW)         // 19200
#define NCHUNK (NCELL/256)             // 1200
#define CHUNKS_PER_B (CELLS_PER_B/256) // 75
#define EPSF 1e-8f
#define FULLM 0xffffffffu

// ---- device scratch (zero-init at load; self-cleaned each run) ----
__device__ float4   g_gt[BB * MGT];     // GT boxes xyxy
__device__ float    g_ga[BB * MGT];     // GT areas
__device__ int      g_cnt[BB];
__device__ unsigned g_mask[NCELL / 32]; // positive-cell bitmask (fully rewritten each run)
__device__ double   g_acc[6];
__device__ unsigned g_bar_arrive;
__device__ unsigned g_bar_gen;
__device__ unsigned g_done;

__device__ __forceinline__ float softplusf(float x) {
    return fmaxf(x, 0.0f) + __logf(1.0f + __expf(-fabsf(x)));
}
__device__ __forceinline__ float wmaxf(float v) {
    #pragma unroll
    for (int o = 16; o > 0; o >>= 1) v = fmaxf(v, __shfl_xor_sync(FULLM, v, o));
    return v;
}
__device__ __forceinline__ float wsumf(float v) {
    #pragma unroll
    for (int o = 16; o > 0; o >>= 1) v += __shfl_xor_sync(FULLM, v, o);
    return v;
}
// select buf[k] from {a,b,c,d} for k in 0..3 (branchless SELs)
__device__ __forceinline__ float sel4(int k, float a, float b, float c, float d) {
    float lo = (k & 1) ? b : a;
    float hi = (k & 1) ? d : c;
    return (k & 2) ? hi : lo;
}

__global__ void __launch_bounds__(256)
k_all(const float* __restrict__ preds, const float* __restrict__ targets,
      float* __restrict__ out, int G) {
    const float AWv[3] = {10.0f, 16.0f, 33.0f};
    const float AHv[3] = {13.0f, 30.0f, 23.0f};
    const int tid = threadIdx.x, bid = blockIdx.x;
    const int lane = tid & 31, wid = tid >> 5;

    // ============ Phase 1: positive bitmask + GT gather ============
    for (int idx = bid * 256 + tid; idx < NCELL; idx += G * 256) {
        float tobj = targets[(size_t)idx * CH + 4];
        bool pos = tobj > 0.0f;
        unsigned pm = __ballot_sync(FULLM, pos);
        if (lane == 0) g_mask[idx >> 5] = pm;
        if (pos) {
            int b  = idx / CELLS_PER_B;
            int r  = idx % CELLS_PER_B;
            int a  = r / (HH * WW);
            int hw = r % (HH * WW);
            float wx = (float)(hw % WW), hy = (float)(hw / WW);
            const float* t = targets + (size_t)idx * CH;
            float cx = (t[0] + wx) * (1.0f / WW);
            float cy = (t[1] + hy) * (1.0f / HH);
            float bw = AWv[a] * __expf(t[2]) * (1.0f / 640.0f);
            float bh = AHv[a] * __expf(t[3]) * (1.0f / 640.0f);
            int slot = atomicAdd(&g_cnt[b], 1);
            if (slot < MGT) {
                g_gt[b * MGT + slot] = make_float4(cx - 0.5f * bw, cy - 0.5f * bh,
                                                   cx + 0.5f * bw, cy + 0.5f * bh);
                g_ga[b * MGT + slot] = bw * bh;
            }
        }
    }

    // ============ Grid barrier (all G blocks co-resident) ============
    __syncthreads();
    if (tid == 0) {
        __threadfence();
        unsigned old = *(volatile unsigned*)&g_bar_gen;
        if (atomicAdd(&g_bar_arrive, 1) == (unsigned)(G - 1)) {
            g_bar_arrive = 0;
            __threadfence();
            atomicAdd(&g_bar_gen, 1);
        } else {
            while (*(volatile unsigned*)&g_bar_gen == old) __nanosleep(64);
        }
        __threadfence();
    }
    __syncthreads();

    // ============ Phase 2: per-cell losses ============
    float acc0 = 0.f, acc1 = 0.f, acc2 = 0.f, acc3 = 0.f, acc4 = 0.f, acc5 = 0.f;

    for (int c = bid; c < NCHUNK; c += G) {
        int b = c / CHUNKS_PER_B;
        int cnt = min(g_cnt[b], MGT);
        float4 gv = g_gt[b * MGT + lane];   // lane l holds GT l
        float  ga = g_ga[b * MGT + lane];

        int idx = c * 256 + tid;
        unsigned pmask = g_mask[idx >> 5];  // warp-uniform word
        bool pos = (pmask >> lane) & 1u;

        // head load: two aligned float4 cover preds[idx*85 + 0..4]
        size_t s = (size_t)idx * CH;
        const float4* pv = (const float4*)preds;
        size_t q = s >> 2;                   // s % 4 == idx % 4
        float4 u = pv[q], v = pv[q + 1];
        int k = idx & 3;
        float p0 = sel4(k, u.x, u.y, u.z, u.w);
        float p1 = sel4(k, u.y, u.z, u.w, v.x);
        float p2 = sel4(k, u.z, u.w, v.x, v.y);
        float p3 = sel4(k, u.w, v.x, v.y, v.z);
        float p4 = sel4(k, v.x, v.y, v.z, v.w);

        int r  = idx % CELLS_PER_B;
        int a  = r / (HH * WW);              // warp-uniform (6400 % 32 == 0)
        int hw = r % (HH * WW);
        float wx = (float)(hw % WW), hy = (float)(hw / WW);
        float aw = AWv[a], ah = AHv[a];

        // conservative warp bbox of all 32 pred boxes
        float twm = wmaxf(p2), thm = wmaxf(p3);
        float hbw = 0.5f * aw * __expf(twm) * (1.0009765625f / 640.0f) + 1e-7f;
        float hbh = 0.5f * ah * __expf(thm) * (1.0009765625f / 640.0f) + 1e-7f;
        int hw0 = (c * 256 + (wid << 5)) % (HH * WW);
        int w0 = hw0 % WW, h0 = hw0 / WW;
        float wxlo, wxhi; float hylo, hyhi;
        if (w0 <= WW - 32) { wxlo = (float)w0; wxhi = (float)(w0 + 31); hylo = (float)h0; hyhi = (float)h0; }
        else               { wxlo = 0.0f;     wxhi = (float)(WW - 1);   hylo = (float)h0; hyhi = (float)(h0 + 1); }
        float bx1 = wxlo * (1.0f / WW) - hbw;
        float bx2 = (wxhi + 1.0f) * (1.0f / WW) + hbw;
        float by1 = hylo * (1.0f / HH) - hbh;
        float by2 = (hyhi + 1.0f) * (1.0f / HH) + hbh;

        bool cand = (lane < cnt) && (gv.x <= bx2) && (gv.z >= bx1) &&
                    (gv.y <= by2) && (gv.w >= by1);
        unsigned cmask = __ballot_sync(FULLM, cand);
        unsigned posm  = __ballot_sync(FULLM, pos);

        float obj_l = softplusf(p4) - p4 * (pos ? 1.0f : 0.0f);

        bool ign = false;
        float giou_l = 0.0f, cls_sum = 0.0f;

        if (cmask | posm) {   // warp-uniform slow path
            float ex = __expf(-p0), ey = __expf(-p1);
            float rr = __fdividef(1.0f, (1.0f + ex) * (1.0f + ey));
            float sx = rr * (1.0f + ey);
            float sy = rr * (1.0f + ex);
            float pcx = (sx + wx) * (1.0f / WW);
            float pcy = (sy + hy) * (1.0f / HH);
            float pbw = aw * __expf(p2) * (1.0f / 640.0f);
            float pbh = ah * __expf(p3) * (1.0f / 640.0f);
            float px1 = pcx - 0.5f * pbw, py1 = pcy - 0.5f * pbh;
            float px2 = pcx + 0.5f * pbw, py2 = pcy + 0.5f * pbh;
            float areaP = pbw * pbh;

            unsigned m = cmask;           // warp-uniform loop
            while (m) {
                int srcl = __ffs(m) - 1; m &= m - 1;
                float gx1 = __shfl_sync(FULLM, gv.x, srcl);
                float gy1 = __shfl_sync(FULLM, gv.y, srcl);
                float gx2 = __shfl_sync(FULLM, gv.z, srcl);
                float gy2 = __shfl_sync(FULLM, gv.w, srcl);
                float gar = __shfl_sync(FULLM, ga,   srcl);
                float iw = fmaxf(fminf(px2, gx2) - fmaxf(px1, gx1), 0.0f);
                float ih = fmaxf(fminf(py2, gy2) - fmaxf(py1, gy1), 0.0f);
                float inter = iw * ih;
                // iou > 0.5  <=>  3*inter > areaP + areaG + eps
                ign |= (3.0f * inter > areaP + gar + EPSF);
            }

            if (pos) {
                const float* t = targets + s;
                float tcx = (t[0] + wx) * (1.0f / WW);
                float tcy = (t[1] + hy) * (1.0f / HH);
                float tbw = aw * __expf(t[2]) * (1.0f / 640.0f);
                float tbh = ah * __expf(t[3]) * (1.0f / 640.0f);
                float tx1 = tcx - 0.5f * tbw, ty1 = tcy - 0.5f * tbh;
                float tx2 = tcx + 0.5f * tbw, ty2 = tcy + 0.5f * tbh;
                float areaT = tbw * tbh;
                float iw = fmaxf(fminf(px2, tx2) - fmaxf(px1, tx1), 0.0f);
                float ih = fmaxf(fminf(py2, ty2) - fmaxf(py1, ty1), 0.0f);
                float inter = iw * ih;
                float uni = areaP + areaT - inter;
                float iou = inter / (uni + EPSF);
                float cw  = fmaxf(fmaxf(px2, tx2) - fminf(px1, tx1), 0.0f);
                float chh = fmaxf(fmaxf(py2, ty2) - fminf(py1, ty1), 0.0f);
                float areaC = cw * chh;
                giou_l = 1.0f - (iou - (areaC - uni) / (areaC + EPSF));

                const float* pf = preds + s;
                #pragma unroll 4
                for (int cc = 0; cc < NC; cc++) {
                    float x  = pf[5 + cc];
                    float tc = t[5 + cc];
                    cls_sum += softplusf(x) - x * tc;
                }
            }
        }

        float posf = pos ? 1.0f : 0.0f;
        float negf = (!pos && !ign) ? 1.0f : 0.0f;
        acc0 += posf;
        acc1 += giou_l;          // already gated to pos lanes
        acc2 += obj_l * posf;
        acc3 += obj_l * negf;
        acc4 += negf;
        acc5 += cls_sum;         // already gated
    }

    // ============ Block reduction + spread atomics ============
    __shared__ float s_red[6][8];
    float vals[6] = {acc0, acc1, acc2, acc3, acc4, acc5};
    #pragma unroll
    for (int kk = 0; kk < 6; kk++) {
        float v = wsumf(vals[kk]);
        if (lane == 0) s_red[kk][wid] = v;
    }
    __syncthreads();
    if (wid == 0 && lane < 6) {
        float v = 0.0f;
        #pragma unroll
        for (int j = 0; j < 8; j++) v += s_red[lane][j];
        atomicAdd(&g_acc[lane], (double)v);
        __threadfence();
    }
    __syncthreads();

    // ============ Last-block finalize + self-clean ============
    if (tid == 0) {
        __threadfence();
        if (atomicAdd(&g_done, 1) == (unsigned)(G - 1)) {
            double npos = atomicAdd(&g_acc[0], 0.0);
            double gsum = atomicAdd(&g_acc[1], 0.0);
            double pobj = atomicAdd(&g_acc[2], 0.0);
            double nobj = atomicAdd(&g_acc[3], 0.0);
            double nneg = atomicAdd(&g_acc[4], 0.0);
            double csum = atomicAdd(&g_acc[5], 0.0);
            float giou_v = (float)(gsum / (npos + (double)EPSF));
            float obj_v  = (float)((5.0 * pobj + nobj) / (5.0 * npos + nneg + (double)EPSF));
            float cls_v  = (float)(csum / (npos + (double)EPSF));
            out[0] = giou_v + obj_v + cls_v;
            out[1] = giou_v;
            out[2] = obj_v;
            out[3] = cls_v;
            #pragma unroll
            for (int kk = 0; kk < 6; kk++) g_acc[kk] = 0.0;
            #pragma unroll
            for (int bb2 = 0; bb2 < BB; bb2++) g_cnt[bb2] = 0;
            g_done = 0;
            __threadfence();
        }
    }
}

extern "C" void kernel_launch(void* const* d_in, const int* in_sizes, int n_in,
                              void* d_out, int out_size) {
    const float* preds   = (const float*)d_in[0];
    const float* targets = (const float*)d_in[1];
    float* out = (float*)d_out;

    int dev = 0;
    cudaGetDevice(&dev);
    int sms = 148;
    cudaDeviceGetAttribute(&sms, cudaDevAttrMultiProcessorCount, dev);
    int occ = 1;
    cudaOccupancyMaxActiveBlocksPerMultiprocessor(&occ, k_all, 256, 0);
    if (occ < 1) occ = 1;
    long long g = (long long)sms * occ;
    if (g > NCHUNK) g = NCHUNK;
    int G = (int)g;

    k_all<<<G, 256>>>(preds, targets, out, G);
}